// round 15
// baseline (speedup 1.0000x reference)
#include <cuda_runtime.h>
#include <cuda_bf16.h>
#include <cstdint>
#include <math.h>

// padded image: 66x66 slots per image, pixel (y,x) at slot (y+1)*66+(x+1)
#define IMG_SLOTS 4356
#define NROW (8 * IMG_SLOTS)   // 34848 padded pixel rows

// ---------------- device scratch (no allocation allowed) ----------------
__device__ float g_tvec[64];
__device__ float g_Qt[8 * 64 * 64 * 64];
__device__ float g_Val[8 * 64 * 64 * 64];
__device__ float g_Lm[8 * 64 * 64];
// transposed mainstream, bf16 hi/lo split, XOR-swizzled rows, per-image pad ring
__device__ __nv_bfloat16 g_m[2][NROW][128];
// B weights prepacked in mma-fragment layout:
// taps: [tap][split][kf][nf(8)][lane(32)][2] u32  (val channels only)
__device__ uint32_t g_Bt[9][2][8][8][32][2];
// center qt/key: [split][kf][nf(16)][lane][2]  (n = 64+qt / 128+key)
__device__ uint32_t g_Bq[2][8][16][32][2];

// ---------------- PTX helpers (ALL baseline sm_80-class features) -------
__device__ __forceinline__ uint32_t smem_u32(const void* p) {
    uint32_t a;
    asm("{ .reg .u64 t; cvta.to.shared.u64 t, %1; cvt.u32.u64 %0, t; }" : "=r"(a) : "l"(p));
    return a;
}
__device__ __forceinline__ void cpa16(uint32_t dst, const void* src, int bytes, int tid) {
    const char* s = (const char*)src;
    for (int o = tid * 16; o < bytes; o += 512 * 16)
        asm volatile("cp.async.cg.shared.global [%0], [%1], 16;" :: "r"(dst + o), "l"(s + o));
}
#define CP_COMMIT() asm volatile("cp.async.commit_group;" ::: "memory")
#define CP_WAIT1()  asm volatile("cp.async.wait_group 1;" ::: "memory")
#define CP_WAIT0()  asm volatile("cp.async.wait_group 0;" ::: "memory")

__device__ __forceinline__ void ldsm4(uint32_t& a0, uint32_t& a1, uint32_t& a2, uint32_t& a3,
                                      uint32_t addr) {
    asm volatile("ldmatrix.sync.aligned.m8n8.x4.shared.b16 {%0,%1,%2,%3}, [%4];"
                 : "=r"(a0), "=r"(a1), "=r"(a2), "=r"(a3) : "r"(addr));
}
__device__ __forceinline__ void lds64(uint32_t& b0, uint32_t& b1, uint32_t addr) {
    asm volatile("ld.shared.v2.u32 {%0,%1}, [%2];" : "=r"(b0), "=r"(b1) : "r"(addr));
}
__device__ __forceinline__ void mma16816(float* d, uint32_t a0, uint32_t a1, uint32_t a2,
                                         uint32_t a3, uint32_t b0, uint32_t b1) {
    asm volatile(
        "mma.sync.aligned.m16n8k16.row.col.f32.bf16.bf16.f32 "
        "{%0,%1,%2,%3}, {%4,%5,%6,%7}, {%8,%9}, {%0,%1,%2,%3};"
        : "+f"(d[0]), "+f"(d[1]), "+f"(d[2]), "+f"(d[3])
        : "r"(a0), "r"(a1), "r"(a2), "r"(a3), "r"(b0), "r"(b1));
}

__device__ __forceinline__ uint32_t pkbf(float v, float* res) {
    __nv_bfloat16 h = __float2bfloat16(v);
    *res = v - __bfloat162float(h);
    return (uint32_t)__bfloat16_as_ushort(h);
}

// ---------------------------------------------------------------------------
// k_prep: direct transpose (blocks 0-2047), pad-zero (2048-2055),
// weight prepack (2056-2144). No smem, no syncs.  (proven R14 version)
// ---------------------------------------------------------------------------
__global__ __launch_bounds__(256) void k_prep(const float* __restrict__ ms,
                                              const float* __restrict__ Wc,
                                              const float* __restrict__ Wf,
                                              const float* __restrict__ bf,
                                              const float* __restrict__ Wk,
                                              const float* __restrict__ Vw) {
    int blk = blockIdx.x, tid = threadIdx.x;
    if (blk < 2048) {
        int id = blk * 256 + tid;            // [0, 524288)
        int x = id & 63;
        int ch = (id >> 6) & 15;
        int y = (id >> 10) & 63;
        int b = id >> 16;
        uint32_t hi[4], lo[4];
#pragma unroll
        for (int ff = 0; ff < 8; ff++) {
            float v = ms[((size_t)(b * 128 + ch * 8 + ff) * 64 + y) * 64 + x];
            __nv_bfloat16 hv = __float2bfloat16(v);
            uint32_t hb = (uint32_t)__bfloat16_as_ushort(hv);
            uint32_t lb = (uint32_t)__bfloat16_as_ushort(
                __float2bfloat16(v - __bfloat162float(hv)));
            if (ff & 1) {
                hi[ff >> 1] |= hb << 16;
                lo[ff >> 1] |= lb << 16;
            } else {
                hi[ff >> 1] = hb;
                lo[ff >> 1] = lb;
            }
        }
        int gr = b * IMG_SLOTS + (y + 1) * 66 + (x + 1);
        int swc = ch ^ (gr & 7);
        *(uint4*)&g_m[0][gr][swc * 8] = *(uint4*)hi;
        *(uint4*)&g_m[1][gr][swc * 8] = *(uint4*)lo;
    } else if (blk < 2056) {
        uint4 z = make_uint4(0, 0, 0, 0);
        int idx = (blk - 2048) * 256 + tid;   // [0, 2048)
        for (int i = idx; i < 66560; i += 2048) {
            int ch = i & 15;
            int t = i >> 4;
            int slot = t % 260;
            int img = (t / 260) % 8;
            int s = t / 2080;
            int r;
            if (slot < 66) r = slot;
            else if (slot < 132) r = 65 * 66 + (slot - 66);
            else {
                int j = slot - 132;
                r = (1 + (j >> 1)) * 66 + ((j & 1) ? 65 : 0);
            }
            *(uint4*)&g_m[s][img * IMG_SLOTS + r][ch * 8] = z;
        }
    } else {
        int T = (blk - 2056) * 256 + tid;
        if (T < 18432) {                       // val taps
            int tap = T / 2048;
            int rem = T & 2047;
            int kf = rem >> 8, nf = (rem >> 5) & 7, l = rem & 31;
            int c = nf * 8 + (l >> 2);
            int ks = kf * 16 + (l & 3) * 2;
            int fj[4] = {ks, ks + 1, ks + 8, ks + 9};
            uint32_t hb[4]; float lo[4];
#pragma unroll
            for (int j = 0; j < 4; j++)
                hb[j] = pkbf(Vw[(c * 128 + fj[j]) * 9 + tap], &lo[j]);
            g_Bt[tap][0][kf][nf][l][0] = hb[0] | (hb[1] << 16);
            g_Bt[tap][0][kf][nf][l][1] = hb[2] | (hb[3] << 16);
            uint32_t lb[4]; float dum;
#pragma unroll
            for (int j = 0; j < 4; j++) lb[j] = pkbf(lo[j], &dum);
            g_Bt[tap][1][kf][nf][l][0] = lb[0] | (lb[1] << 16);
            g_Bt[tap][1][kf][nf][l][1] = lb[2] | (lb[3] << 16);
        } else if (T < 22528) {                // center qt/key
            int T2 = T - 18432;
            int kf = T2 >> 9, nf = (T2 >> 5) & 15, l = T2 & 31;
            int n = nf * 8 + (l >> 2);
            int ks = kf * 16 + (l & 3) * 2;
            int fj[4] = {ks, ks + 1, ks + 8, ks + 9};
            uint32_t hb[4], lb[4]; float lo[4], dum;
#pragma unroll
            for (int j = 0; j < 4; j++) {
                float v;
                if (n < 64) {
                    v = 0.f;
                    for (int d = 0; d < 64; d++)
                        v = fmaf(Wc[d * 64 + n], Wf[d * 128 + fj[j]], v);
                } else {
                    v = Wk[(n - 64) * 128 + fj[j]];
                }
                hb[j] = pkbf(v, &lo[j]);
                lb[j] = pkbf(lo[j], &dum);
            }
            g_Bq[0][kf][nf][l][0] = hb[0] | (hb[1] << 16);
            g_Bq[0][kf][nf][l][1] = hb[2] | (hb[3] << 16);
            g_Bq[1][kf][nf][l][0] = lb[0] | (lb[1] << 16);
            g_Bq[1][kf][nf][l][1] = lb[2] | (lb[3] << 16);
        } else if (T < 22592) {                // tvec
            int c = T - 22528;
            float t = 0.f;
            for (int d = 0; d < 64; d++) t = fmaf(Wc[d * 64 + c], bf[d], t);
            g_tvec[c] = t;
        }
    }
}

// ---------------------------------------------------------------------------
// k1: mma.sync implicit GEMM, triple-buffered B, ONE sync per iteration.
// 256 blocks x 512 threads, 128 pixels/block.
// ---------------------------------------------------------------------------
#define AS_OFF 0               // 264 rows * 256B = 67584
#define BS0 67584
#define BS1 100352
#define BS2 133120
#define QS_OFF 165888          // 65536
#define SB_OFF 231424          // 768 bias region (never overwritten)
#define SMEM_K1 232192
// epilogue overlay (B/A regions dead by then):
#define SV_OFF 0
#define SQ_OFF 33792
#define SK_OFF 67584

__global__ __launch_bounds__(512, 1) void k1_mma(const float* __restrict__ Vb,
                                                 const float* __restrict__ bk) {
    extern __shared__ char smc[];
    uint32_t sb = smem_u32(smc);
    float* smf = (float*)smc;

    const int tid = threadIdx.x;
    const int lane = tid & 31, w = tid >> 5;
    const int mf = w & 7, nh = w >> 3;
    const int p0 = blockIdx.x * 128;
    const int bb = p0 >> 12, yy = (p0 >> 6) & 63;
    const int slabstart = bb * IMG_SLOTS + yy * 66;
    const int lr = (lane & 7) + (lane & 8);
    const int chi = lane >> 4;
    const int mfbase = 67 + mf * 16 + ((mf >= 4) ? 2 : 0);

    if (tid < 64) {
        smf[SB_OFF / 4 + tid] = bk[tid];
        smf[SB_OFF / 4 + 64 + tid] = g_tvec[tid];
        smf[SB_OFF / 4 + 128 + tid] = Vb[tid];
    }

    // preload: group0 = {A_hi, Q, item0}, group1 = {item1}
    cpa16(sb + AS_OFF, &g_m[0][slabstart][0], 67584, tid);
    cpa16(sb + QS_OFF, &g_Bq[0][0][0][0][0], 65536, tid);
    cpa16(sb + BS0, &g_Bt[0][0][0][0][0][0], 32768, tid);
    CP_COMMIT();
    cpa16(sb + BS1, &g_Bt[1][0][0][0][0][0], 32768, tid);
    CP_COMMIT();

    float aV[4][4], aQ[8][4];
#pragma unroll
    for (int j = 0; j < 4; j++)
#pragma unroll
        for (int u = 0; u < 4; u++) aV[j][u] = 0.f;
#pragma unroll
    for (int j = 0; j < 8; j++)
#pragma unroll
        for (int u = 0; u < 4; u++) aQ[j][u] = 0.f;

    const uint32_t bofs[3] = {BS0, BS1, BS2};

#pragma unroll 1
    for (int it = 0; it < 18; it++) {
        const int phase = (it >= 9) ? 1 : 0;
        const int t = it - phase * 9;

        CP_WAIT1();          // item `it` resident (newest group = item it+1)
        __syncthreads();     // visibility + everyone past compute(it-1)

        if (it == 9) {
            // phase boundary: compute(8) done (sync above) -> safe to swap A
            cpa16(sb + AS_OFF, &g_m[1][slabstart][0], 67584, tid);
        }
        int nx = it + 2;
        if (nx < 18) {
            int p2 = (nx >= 9) ? 1 : 0;
            int t2 = nx - p2 * 9;
            // target buf consumed at compute(it-1); guarded by sync above
            cpa16(sb + bofs[nx % 3], &g_Bt[t2][0][0][0][0][0],
                  p2 ? 16384 : 32768, tid);
        }
        CP_COMMIT();
        if (it == 9) {       // A_lo must be resident before compute
            CP_WAIT0();
            __syncthreads();
        }

        const uint32_t bbuf = bofs[it % 3];
        int dy = t / 3, dx = t - dy * 3;
        int off = (dy - 1) * 66 + (dx - 1);
        int relrow = mfbase + off + lr;
        uint32_t abase = sb + AS_OFF + (uint32_t)relrow * 256;
        int rph = (slabstart + relrow) & 7;

        // hoisted A fragments: load once per tap, reuse across B passes
        uint32_t af[8][4];
#pragma unroll
        for (int kf = 0; kf < 8; kf++)
            ldsm4(af[kf][0], af[kf][1], af[kf][2], af[kf][3],
                  abase + ((((kf << 1) + chi) ^ rph) << 4));

        int passes = phase ? 1 : 2;
#pragma unroll 1
        for (int sB = 0; sB < passes; sB++) {
            uint32_t Bb = sb + bbuf + sB * 16384;
            uint32_t Qb = sb + QS_OFF + sB * 32768;
#pragma unroll
            for (int kf = 0; kf < 8; kf++) {
#pragma unroll
                for (int j = 0; j < 4; j++) {
                    int nf = nh * 4 + j;
                    uint32_t b0, b1;
                    lds64(b0, b1, Bb + ((kf * 8 + nf) * 32 + lane) * 8);
                    mma16816(aV[j], af[kf][0], af[kf][1], af[kf][2], af[kf][3], b0, b1);
                }
                if (t == 4) {
#pragma unroll
                    for (int j = 0; j < 8; j++) {
                        int qf = nh * 8 + j;
                        uint32_t b0, b1;
                        lds64(b0, b1, Qb + ((kf * 16 + qf) * 32 + lane) * 8);
                        mma16816(aQ[j], af[kf][0], af[kf][1], af[kf][2], af[kf][3], b0, b1);
                    }
                }
            }
        }
    }
    __syncthreads();   // all compute done before epilogue overlays smem

    // ---- epilogue: stage D to smem (overlay), then coalesced writeout ----
    const int r0 = mf * 16 + (lane >> 2);
#pragma unroll
    for (int j = 0; j < 4; j++) {
        int c0 = (nh * 4 + j) * 8 + (lane & 3) * 2;
        smf[SV_OFF / 4 + c0 * 132 + r0] = aV[j][0];
        smf[SV_OFF / 4 + (c0 + 1) * 132 + r0] = aV[j][1];
        smf[SV_OFF / 4 + c0 * 132 + r0 + 8] = aV[j][2];
        smf[SV_OFF / 4 + (c0 + 1) * 132 + r0 + 8] = aV[j][3];
    }
#pragma unroll
    for (int j = 0; j < 8; j++) {
        int nq = (nh * 8 + j) * 8 + (lane & 3) * 2;
        int base = (nq < 64) ? SQ_OFF / 4 : SK_OFF / 4;
        int cc = nq & 63;
        smf[base + cc * 132 + r0] = aQ[j][0];
        smf[base + (cc + 1) * 132 + r0] = aQ[j][1];
        smf[base + cc * 132 + r0 + 8] = aQ[j][2];
        smf[base + (cc + 1) * 132 + r0 + 8] = aQ[j][3];
    }
    __syncthreads();

#pragma unroll
    for (int rep = 0; rep < 16; rep++) {
        int idx = rep * 512 + tid;
        int c = idx >> 7, px = idx & 127;
        int p = p0 + px;
        int gi = ((p >> 12) * 64 + c) * 4096 + (p & 4095);
        g_Val[gi] = smf[SV_OFF / 4 + c * 132 + px] + smf[SB_OFF / 4 + 128 + c];
        g_Qt[gi] = smf[SQ_OFF / 4 + c * 132 + px] + smf[SB_OFF / 4 + 64 + c];
    }
    {
        int px = tid >> 2, q = tid & 3;
        float s = 0.f;
#pragma unroll 4
        for (int cc = q * 16; cc < q * 16 + 16; cc++) {
            float key = smf[SK_OFF / 4 + cc * 132 + px] + smf[SB_OFF / 4 + cc];
            float qt = smf[SQ_OFF / 4 + cc * 132 + px] + smf[SB_OFF / 4 + 64 + cc];
            s = fmaf(key, qt, s);
        }
        s += __shfl_down_sync(0xffffffffu, s, 1);
        s += __shfl_down_sync(0xffffffffu, s, 2);
        if (q == 0) {
            int p = p0 + px;
            g_Lm[(p >> 12) * 4096 + (p & 4095)] = s;
        }
    }
}

// ---------------------------------------------------------------------------
// k2: high-res attention, 4-way channel split (proven version, ~41us).
// ---------------------------------------------------------------------------
__global__ __launch_bounds__(256) void k2_highres(const float* __restrict__ ctx,
                                                  float* __restrict__ out) {
    int idx = blockIdx.x * 256 + threadIdx.x;    // 262144 threads
    int q = idx & 3;
    int pp = idx >> 2;                           // pixel-pair id [0, 65536)
    int b = pp >> 13;
    int rem = pp & 8191;
    int hr = rem >> 6;
    int x = rem & 63;
    int y = hr >> 1;
    int c0 = q * 16;

    const float* qt = g_Qt + ((b * 64 + c0) * 64 + y) * 64 + x;
    const float2* cp2 = (const float2*)(ctx + (size_t)b * 3 * 64 * 16384 + hr * 128)
                        + x + (size_t)c0 * 8192;

    float2 l0 = make_float2(0.f, 0.f), l1 = l0, l2 = l0;
#pragma unroll 4
    for (int c = 0; c < 16; c++) {
        float qv = qt[c * 4096];
        float2 a = cp2[c * 8192];
        float2 d = cp2[(64 + c) * 8192];
        float2 e = cp2[(128 + c) * 8192];
        l0.x = fmaf(a.x, qv, l0.x); l0.y = fmaf(a.y, qv, l0.y);
        l1.x = fmaf(d.x, qv, l1.x); l1.y = fmaf(d.y, qv, l1.y);
        l2.x = fmaf(e.x, qv, l2.x); l2.y = fmaf(e.y, qv, l2.y);
    }
#pragma unroll
    for (int m = 1; m <= 2; m <<= 1) {
        l0.x += __shfl_xor_sync(0xffffffffu, l0.x, m);
        l0.y += __shfl_xor_sync(0xffffffffu, l0.y, m);
        l1.x += __shfl_xor_sync(0xffffffffu, l1.x, m);
        l1.y += __shfl_xor_sync(0xffffffffu, l1.y, m);
        l2.x += __shfl_xor_sync(0xffffffffu, l2.x, m);
        l2.y += __shfl_xor_sync(0xffffffffu, l2.y, m);
    }
    float l3 = g_Lm[(b * 64 + y) * 64 + x];

    float2 w0, w1, w2, w3;
    {
        float mx = fmaxf(fmaxf(l0.x, l1.x), fmaxf(l2.x, l3));
        float e0 = __expf(l0.x - mx), e1 = __expf(l1.x - mx);
        float e2 = __expf(l2.x - mx), e3 = __expf(l3 - mx);
        float inv = 1.f / (e0 + e1 + e2 + e3);
        w0.x = e0 * inv; w1.x = e1 * inv; w2.x = e2 * inv; w3.x = e3 * inv;
    }
    {
        float mx = fmaxf(fmaxf(l0.y, l1.y), fmaxf(l2.y, l3));
        float e0 = __expf(l0.y - mx), e1 = __expf(l1.y - mx);
        float e2 = __expf(l2.y - mx), e3 = __expf(l3 - mx);
        float inv = 1.f / (e0 + e1 + e2 + e3);
        w0.y = e0 * inv; w1.y = e1 * inv; w2.y = e2 * inv; w3.y = e3 * inv;
    }

    const float* vp = g_Val + ((b * 64 + c0) * 64 + y) * 64 + x;
    float2* op = (float2*)(out + (size_t)(b * 64 + c0) * 16384 + hr * 128) + x;
#pragma unroll 4
    for (int c = 0; c < 16; c++) {
        float v = vp[c * 4096];
        float2 a = cp2[c * 8192];
        float2 d = cp2[(64 + c) * 8192];
        float2 e = cp2[(128 + c) * 8192];
        float2 o;
        o.x = w3.x * v; o.y = w3.y * v;
        o.x = fmaf(w0.x, a.x, o.x); o.y = fmaf(w0.y, a.y, o.y);
        o.x = fmaf(w1.x, d.x, o.x); o.y = fmaf(w1.y, d.y, o.y);
        o.x = fmaf(w2.x, e.x, o.x); o.y = fmaf(w2.y, e.y, o.y);
        op[c * 8192] = o;
    }
}

// ---------------------------------------------------------------------------
extern "C" void kernel_launch(void* const* d_in, const int* in_sizes, int n_in,
                              void* d_out, int out_size) {
    (void)in_sizes; (void)n_in; (void)out_size;
    const float* contexts = (const float*)d_in[0];
    const float* mainstream = (const float*)d_in[1];
    const float* Wc = (const float*)d_in[2];
    // d_in[3] = bc : cancels in softmax, unused
    const float* Wf = (const float*)d_in[4];
    const float* bf = (const float*)d_in[5];
    const float* Wk = (const float*)d_in[6];
    const float* bk = (const float*)d_in[7];
    const float* Vw = (const float*)d_in[8];
    const float* Vb = (const float*)d_in[9];
    float* out = (float*)d_out;

    cudaFuncSetAttribute(k1_mma, cudaFuncAttributeMaxDynamicSharedMemorySize, SMEM_K1);

    k_prep<<<2145, 256>>>(mainstream, Wc, Wf, bf, Wk, Vw);
    k1_mma<<<256, 512, SMEM_K1>>>(Vb, bk);
    k2_highres<<<1024, 256>>>(contexts, out);
}

// round 16
// speedup vs baseline: 1.0275x; 1.0275x over previous
#include <cuda_runtime.h>
#include <cuda_bf16.h>
#include <cstdint>
#include <math.h>

// padded image: 66x66 slots per image, pixel (y,x) at slot (y+1)*66+(x+1)
#define IMG_SLOTS 4356
#define NROW (8 * IMG_SLOTS)   // 34848 padded pixel rows

// ---------------- device scratch (no allocation allowed) ----------------
__device__ float g_tvec[64];
__device__ float g_Qt[8 * 64 * 64 * 64];
__device__ float g_Val[8 * 64 * 64 * 64];
__device__ float g_Lm[8 * 64 * 64];
// transposed mainstream, bf16 hi/lo split, CHUNK-MAJOR: [split][chunk][pixelrow]
// each uint4 = 8 bf16 (f values chunk*8..chunk*8+7) of one padded pixel row
__device__ uint4 g_m4[2][16][NROW];
// B weights prepacked in mma-fragment layout:
// taps: [tap][split][kf][nf(8)][lane(32)][2] u32  (val channels only)
__device__ uint32_t g_Bt[9][2][8][8][32][2];
// center qt/key: [split][kf][nf(16)][lane][2]  (n = 64+qt / 128+key)
__device__ uint32_t g_Bq[2][8][16][32][2];

// ---------------- PTX helpers (ALL baseline sm_80-class features) -------
__device__ __forceinline__ uint32_t smem_u32(const void* p) {
    uint32_t a;
    asm("{ .reg .u64 t; cvta.to.shared.u64 t, %1; cvt.u32.u64 %0, t; }" : "=r"(a) : "l"(p));
    return a;
}
__device__ __forceinline__ void cpa16(uint32_t dst, const void* src, int bytes, int tid) {
    const char* s = (const char*)src;
    for (int o = tid * 16; o < bytes; o += 512 * 16)
        asm volatile("cp.async.cg.shared.global [%0], [%1], 16;" :: "r"(dst + o), "l"(s + o));
}
// strided A-slab copy: 16 chunks x nrows 16B rows; smem pitch 4224B per chunk
__device__ __forceinline__ void cpa_slab(uint32_t dst, const uint4* srcbase,
                                         int slabstart, int tid) {
    for (int i = tid; i < 16 * 264; i += 512) {
        int c = i / 264, r = i - c * 264;
        asm volatile("cp.async.cg.shared.global [%0], [%1], 16;"
                     :: "r"(dst + c * 4224 + r * 16),
                        "l"(srcbase + (size_t)c * NROW + slabstart + r));
    }
}
#define CP_COMMIT() asm volatile("cp.async.commit_group;" ::: "memory")
#define CP_WAIT1()  asm volatile("cp.async.wait_group 1;" ::: "memory")
#define CP_WAIT0()  asm volatile("cp.async.wait_group 0;" ::: "memory")

__device__ __forceinline__ void ldsm4(uint32_t& a0, uint32_t& a1, uint32_t& a2, uint32_t& a3,
                                      uint32_t addr) {
    asm volatile("ldmatrix.sync.aligned.m8n8.x4.shared.b16 {%0,%1,%2,%3}, [%4];"
                 : "=r"(a0), "=r"(a1), "=r"(a2), "=r"(a3) : "r"(addr));
}
__device__ __forceinline__ void lds64(uint32_t& b0, uint32_t& b1, uint32_t addr) {
    asm volatile("ld.shared.v2.u32 {%0,%1}, [%2];" : "=r"(b0), "=r"(b1) : "r"(addr));
}
__device__ __forceinline__ void mma16816(float* d, uint32_t a0, uint32_t a1, uint32_t a2,
                                         uint32_t a3, uint32_t b0, uint32_t b1) {
    asm volatile(
        "mma.sync.aligned.m16n8k16.row.col.f32.bf16.bf16.f32 "
        "{%0,%1,%2,%3}, {%4,%5,%6,%7}, {%8,%9}, {%0,%1,%2,%3};"
        : "+f"(d[0]), "+f"(d[1]), "+f"(d[2]), "+f"(d[3])
        : "r"(a0), "r"(a1), "r"(a2), "r"(a3), "r"(b0), "r"(b1));
}

__device__ __forceinline__ uint32_t pkbf(float v, float* res) {
    __nv_bfloat16 h = __float2bfloat16(v);
    *res = v - __bfloat162float(h);
    return (uint32_t)__bfloat16_as_ushort(h);
}

// ---------------------------------------------------------------------------
// k_prep: direct transpose (blocks 0-2047), pad-zero (2048-2055),
// weight prepack (2056-2144). Chunk-major g_m4 -> fully coalesced stores.
// ---------------------------------------------------------------------------
__global__ __launch_bounds__(256) void k_prep(const float* __restrict__ ms,
                                              const float* __restrict__ Wc,
                                              const float* __restrict__ Wf,
                                              const float* __restrict__ bf,
                                              const float* __restrict__ Wk,
                                              const float* __restrict__ Vw) {
    int blk = blockIdx.x, tid = threadIdx.x;
    if (blk < 2048) {
        int id = blk * 256 + tid;            // [0, 524288)
        int x = id & 63;
        int ch = (id >> 6) & 15;
        int y = (id >> 10) & 63;
        int b = id >> 16;
        uint32_t hi[4], lo[4];
#pragma unroll
        for (int ff = 0; ff < 8; ff++) {
            float v = ms[((size_t)(b * 128 + ch * 8 + ff) * 64 + y) * 64 + x];
            __nv_bfloat16 hv = __float2bfloat16(v);
            uint32_t hb = (uint32_t)__bfloat16_as_ushort(hv);
            uint32_t lb = (uint32_t)__bfloat16_as_ushort(
                __float2bfloat16(v - __bfloat162float(hv)));
            if (ff & 1) {
                hi[ff >> 1] |= hb << 16;
                lo[ff >> 1] |= lb << 16;
            } else {
                hi[ff >> 1] = hb;
                lo[ff >> 1] = lb;
            }
        }
        int gr = b * IMG_SLOTS + (y + 1) * 66 + (x + 1);
        g_m4[0][ch][gr] = *(uint4*)hi;       // coalesced: consecutive x -> consecutive uint4
        g_m4[1][ch][gr] = *(uint4*)lo;
    } else if (blk < 2056) {
        // zero pad rings: 2 splits x 16 chunks x 8 imgs x 260 slots
        uint4 z = make_uint4(0, 0, 0, 0);
        int idx = (blk - 2048) * 256 + tid;   // [0, 2048)
        for (int i = idx; i < 66560; i += 2048) {
            int ch = i & 15;
            int t = i >> 4;
            int slot = t % 260;
            int img = (t / 260) % 8;
            int s = t / 2080;
            int r;
            if (slot < 66) r = slot;
            else if (slot < 132) r = 65 * 66 + (slot - 66);
            else {
                int j = slot - 132;
                r = (1 + (j >> 1)) * 66 + ((j & 1) ? 65 : 0);
            }
            g_m4[s][ch][img * IMG_SLOTS + r] = z;
        }
    } else {
        int T = (blk - 2056) * 256 + tid;
        if (T < 18432) {                       // val taps
            int tap = T / 2048;
            int rem = T & 2047;
            int kf = rem >> 8, nf = (rem >> 5) & 7, l = rem & 31;
            int c = nf * 8 + (l >> 2);
            int ks = kf * 16 + (l & 3) * 2;
            int fj[4] = {ks, ks + 1, ks + 8, ks + 9};
            uint32_t hb[4]; float lo[4];
#pragma unroll
            for (int j = 0; j < 4; j++)
                hb[j] = pkbf(Vw[(c * 128 + fj[j]) * 9 + tap], &lo[j]);
            g_Bt[tap][0][kf][nf][l][0] = hb[0] | (hb[1] << 16);
            g_Bt[tap][0][kf][nf][l][1] = hb[2] | (hb[3] << 16);
            uint32_t lb[4]; float dum;
#pragma unroll
            for (int j = 0; j < 4; j++) lb[j] = pkbf(lo[j], &dum);
            g_Bt[tap][1][kf][nf][l][0] = lb[0] | (lb[1] << 16);
            g_Bt[tap][1][kf][nf][l][1] = lb[2] | (lb[3] << 16);
        } else if (T < 22528) {                // center qt/key
            int T2 = T - 18432;
            int kf = T2 >> 9, nf = (T2 >> 5) & 15, l = T2 & 31;
            int n = nf * 8 + (l >> 2);
            int ks = kf * 16 + (l & 3) * 2;
            int fj[4] = {ks, ks + 1, ks + 8, ks + 9};
            uint32_t hb[4], lb[4]; float lo[4], dum;
#pragma unroll
            for (int j = 0; j < 4; j++) {
                float v;
                if (n < 64) {
                    v = 0.f;
                    for (int d = 0; d < 64; d++)
                        v = fmaf(Wc[d * 64 + n], Wf[d * 128 + fj[j]], v);
                } else {
                    v = Wk[(n - 64) * 128 + fj[j]];
                }
                hb[j] = pkbf(v, &lo[j]);
                lb[j] = pkbf(lo[j], &dum);
            }
            g_Bq[0][kf][nf][l][0] = hb[0] | (hb[1] << 16);
            g_Bq[0][kf][nf][l][1] = hb[2] | (hb[3] << 16);
            g_Bq[1][kf][nf][l][0] = lb[0] | (lb[1] << 16);
            g_Bq[1][kf][nf][l][1] = lb[2] | (lb[3] << 16);
        } else if (T < 22592) {                // tvec
            int c = T - 22528;
            float t = 0.f;
            for (int d = 0; d < 64; d++) t = fmaf(Wc[d * 64 + c], bf[d], t);
            g_tvec[c] = t;
        }
    }
}

// ---------------------------------------------------------------------------
// k1: mma.sync implicit GEMM (proven R14 double-buffer pipeline).
// A slab chunk-major: smem [16 chunks][264 rows][16B]; no swizzle needed.
// ---------------------------------------------------------------------------
#define AS_OFF 0               // 16 * 264 * 16 = 67584
#define B0_OFF 67584
#define B1_OFF 100352
#define QS_OFF 133120
#define SV_OFF 0
#define SQ_OFF 33792
#define SK_OFF 67584
#define SB_OFF 198656
#define SMEM_K1 199424

__global__ __launch_bounds__(512, 1) void k1_mma(const float* __restrict__ Vb,
                                                 const float* __restrict__ bk) {
    extern __shared__ char smc[];
    uint32_t sb = smem_u32(smc);
    float* smf = (float*)smc;

    const int tid = threadIdx.x;
    const int lane = tid & 31, w = tid >> 5;
    const int mf = w & 7, nh = w >> 3;
    const int p0 = blockIdx.x * 128;
    const int bb = p0 >> 12, yy = (p0 >> 6) & 63;
    const int slabstart = bb * IMG_SLOTS + yy * 66;
    const int lr = (lane & 7) + (lane & 8);
    const int chi = lane >> 4;
    const int mfbase = 67 + mf * 16 + ((mf >= 4) ? 2 : 0);

    if (tid < 64) {
        smf[SB_OFF / 4 + tid] = bk[tid];
        smf[SB_OFF / 4 + 64 + tid] = g_tvec[tid];
        smf[SB_OFF / 4 + 128 + tid] = Vb[tid];
    }

    cpa_slab(sb + AS_OFF, &g_m4[0][0][0], slabstart, tid);
    cpa16(sb + QS_OFF, &g_Bq[0][0][0][0][0], 65536, tid);
    CP_COMMIT();
    cpa16(sb + B0_OFF, &g_Bt[0][0][0][0][0][0], 32768, tid);
    CP_COMMIT();

    float aV[4][4], aQ[8][4];
#pragma unroll
    for (int j = 0; j < 4; j++)
#pragma unroll
        for (int u = 0; u < 4; u++) aV[j][u] = 0.f;
#pragma unroll
    for (int j = 0; j < 8; j++)
#pragma unroll
        for (int u = 0; u < 4; u++) aQ[j][u] = 0.f;

#pragma unroll 1
    for (int phase = 0; phase < 2; phase++) {
#pragma unroll 1
        for (int t = 0; t < 9; t++) {
            uint32_t bbuf = (t & 1) ? B1_OFF : B0_OFF;
            uint32_t nbuf = (t & 1) ? B0_OFF : B1_OFF;
            if (t < 8) {
                if (phase == 0)
                    cpa16(sb + nbuf, &g_Bt[t + 1][0][0][0][0][0], 32768, tid);
                else
                    cpa16(sb + nbuf, &g_Bt[t + 1][0][0][0][0][0], 16384, tid);
                CP_COMMIT();
                CP_WAIT1();
            } else {
                CP_WAIT0();
            }
            __syncthreads();

            int dy = t / 3, dx = t - dy * 3;
            int off = (dy - 1) * 66 + (dx - 1);
            int relrow = mfbase + off + lr;

            // hoisted A fragments: chunk-major, conflict-free, no XOR
            uint32_t af[8][4];
#pragma unroll
            for (int kf = 0; kf < 8; kf++)
                ldsm4(af[kf][0], af[kf][1], af[kf][2], af[kf][3],
                      sb + AS_OFF + (uint32_t)((kf * 2 + chi) * 4224 + relrow * 16));

            int passes = phase ? 1 : 2;
#pragma unroll 1
            for (int sB = 0; sB < passes; sB++) {
                uint32_t Bb = sb + bbuf + sB * 16384;
                uint32_t Qb = sb + QS_OFF + sB * 32768;
#pragma unroll
                for (int kf = 0; kf < 8; kf++) {
#pragma unroll
                    for (int j = 0; j < 4; j++) {
                        int nf = nh * 4 + j;
                        uint32_t b0, b1;
                        lds64(b0, b1, Bb + ((kf * 8 + nf) * 32 + lane) * 8);
                        mma16816(aV[j], af[kf][0], af[kf][1], af[kf][2], af[kf][3], b0, b1);
                    }
                    if (t == 4) {
#pragma unroll
                        for (int j = 0; j < 8; j++) {
                            int qf = nh * 8 + j;
                            uint32_t b0, b1;
                            lds64(b0, b1, Qb + ((kf * 16 + qf) * 32 + lane) * 8);
                            mma16816(aQ[j], af[kf][0], af[kf][1], af[kf][2], af[kf][3], b0, b1);
                        }
                    }
                }
            }
            __syncthreads();
        }
        if (phase == 0) {
            cpa_slab(sb + AS_OFF, &g_m4[1][0][0], slabstart, tid);   // A lo slab
            cpa16(sb + B0_OFF, &g_Bt[0][0][0][0][0][0], 16384, tid);
            CP_COMMIT();
        }
    }

    // ---- epilogue: stage D to smem (overlay), then coalesced writeout ----
    const int r0 = mf * 16 + (lane >> 2);
#pragma unroll
    for (int j = 0; j < 4; j++) {
        int c0 = (nh * 4 + j) * 8 + (lane & 3) * 2;
        smf[SV_OFF / 4 + c0 * 132 + r0] = aV[j][0];
        smf[SV_OFF / 4 + (c0 + 1) * 132 + r0] = aV[j][1];
        smf[SV_OFF / 4 + c0 * 132 + r0 + 8] = aV[j][2];
        smf[SV_OFF / 4 + (c0 + 1) * 132 + r0 + 8] = aV[j][3];
    }
#pragma unroll
    for (int j = 0; j < 8; j++) {
        int nq = (nh * 8 + j) * 8 + (lane & 3) * 2;
        int base = (nq < 64) ? SQ_OFF / 4 : SK_OFF / 4;
        int cc = nq & 63;
        smf[base + cc * 132 + r0] = aQ[j][0];
        smf[base + (cc + 1) * 132 + r0] = aQ[j][1];
        smf[base + cc * 132 + r0 + 8] = aQ[j][2];
        smf[base + (cc + 1) * 132 + r0 + 8] = aQ[j][3];
    }
    __syncthreads();

#pragma unroll
    for (int rep = 0; rep < 16; rep++) {
        int idx = rep * 512 + tid;
        int c = idx >> 7, px = idx & 127;
        int p = p0 + px;
        int gi = ((p >> 12) * 64 + c) * 4096 + (p & 4095);
        g_Val[gi] = smf[SV_OFF / 4 + c * 132 + px] + smf[SB_OFF / 4 + 128 + c];
        g_Qt[gi] = smf[SQ_OFF / 4 + c * 132 + px] + smf[SB_OFF / 4 + 64 + c];
    }
    {
        int px = tid >> 2, q = tid & 3;
        float s = 0.f;
#pragma unroll 4
        for (int cc = q * 16; cc < q * 16 + 16; cc++) {
            float key = smf[SK_OFF / 4 + cc * 132 + px] + smf[SB_OFF / 4 + cc];
            float qt = smf[SQ_OFF / 4 + cc * 132 + px] + smf[SB_OFF / 4 + 64 + cc];
            s = fmaf(key, qt, s);
        }
        s += __shfl_down_sync(0xffffffffu, s, 1);
        s += __shfl_down_sync(0xffffffffu, s, 2);
        if (q == 0) {
            int p = p0 + px;
            g_Lm[(p >> 12) * 4096 + (p & 4095)] = s;
        }
    }
}

// ---------------------------------------------------------------------------
// k2: high-res attention, 4-way channel split (proven version, ~41us).
// ---------------------------------------------------------------------------
__global__ __launch_bounds__(256) void k2_highres(const float* __restrict__ ctx,
                                                  float* __restrict__ out) {
    int idx = blockIdx.x * 256 + threadIdx.x;    // 262144 threads
    int q = idx & 3;
    int pp = idx >> 2;                           // pixel-pair id [0, 65536)
    int b = pp >> 13;
    int rem = pp & 8191;
    int hr = rem >> 6;
    int x = rem & 63;
    int y = hr >> 1;
    int c0 = q * 16;

    const float* qt = g_Qt + ((b * 64 + c0) * 64 + y) * 64 + x;
    const float2* cp2 = (const float2*)(ctx + (size_t)b * 3 * 64 * 16384 + hr * 128)
                        + x + (size_t)c0 * 8192;

    float2 l0 = make_float2(0.f, 0.f), l1 = l0, l2 = l0;
#pragma unroll 4
    for (int c = 0; c < 16; c++) {
        float qv = qt[c * 4096];
        float2 a = cp2[c * 8192];
        float2 d = cp2[(64 + c) * 8192];
        float2 e = cp2[(128 + c) * 8192];
        l0.x = fmaf(a.x, qv, l0.x); l0.y = fmaf(a.y, qv, l0.y);
        l1.x = fmaf(d.x, qv, l1.x); l1.y = fmaf(d.y, qv, l1.y);
        l2.x = fmaf(e.x, qv, l2.x); l2.y = fmaf(e.y, qv, l2.y);
    }
#pragma unroll
    for (int m = 1; m <= 2; m <<= 1) {
        l0.x += __shfl_xor_sync(0xffffffffu, l0.x, m);
        l0.y += __shfl_xor_sync(0xffffffffu, l0.y, m);
        l1.x += __shfl_xor_sync(0xffffffffu, l1.x, m);
        l1.y += __shfl_xor_sync(0xffffffffu, l1.y, m);
        l2.x += __shfl_xor_sync(0xffffffffu, l2.x, m);
        l2.y += __shfl_xor_sync(0xffffffffu, l2.y, m);
    }
    float l3 = g_Lm[(b * 64 + y) * 64 + x];

    float2 w0, w1, w2, w3;
    {
        float mx = fmaxf(fmaxf(l0.x, l1.x), fmaxf(l2.x, l3));
        float e0 = __expf(l0.x - mx), e1 = __expf(l1.x - mx);
        float e2 = __expf(l2.x - mx), e3 = __expf(l3 - mx);
        float inv = 1.f / (e0 + e1 + e2 + e3);
        w0.x = e0 * inv; w1.x = e1 * inv; w2.x = e2 * inv; w3.x = e3 * inv;
    }
    {
        float mx = fmaxf(fmaxf(l0.y, l1.y), fmaxf(l2.y, l3));
        float e0 = __expf(l0.y - mx), e1 = __expf(l1.y - mx);
        float e2 = __expf(l2.y - mx), e3 = __expf(l3 - mx);
        float inv = 1.f / (e0 + e1 + e2 + e3);
        w0.y = e0 * inv; w1.y = e1 * inv; w2.y = e2 * inv; w3.y = e3 * inv;
    }

    const float* vp = g_Val + ((b * 64 + c0) * 64 + y) * 64 + x;
    float2* op = (float2*)(out + (size_t)(b * 64 + c0) * 16384 + hr * 128) + x;
#pragma unroll 4
    for (int c = 0; c < 16; c++) {
        float v = vp[c * 4096];
        float2 a = cp2[c * 8192];
        float2 d = cp2[(64 + c) * 8192];
        float2 e = cp2[(128 + c) * 8192];
        float2 o;
        o.x = w3.x * v; o.y = w3.y * v;
        o.x = fmaf(w0.x, a.x, o.x); o.y = fmaf(w0.y, a.y, o.y);
        o.x = fmaf(w1.x, d.x, o.x); o.y = fmaf(w1.y, d.y, o.y);
        o.x = fmaf(w2.x, e.x, o.x); o.y = fmaf(w2.y, e.y, o.y);
        op[c * 8192] = o;
    }
}

// ---------------------------------------------------------------------------
extern "C" void kernel_launch(void* const* d_in, const int* in_sizes, int n_in,
                              void* d_out, int out_size) {
    (void)in_sizes; (void)n_in; (void)out_size;
    const float* contexts = (const float*)d_in[0];
    const float* mainstream = (const float*)d_in[1];
    const float* Wc = (const float*)d_in[2];
    // d_in[3] = bc : cancels in softmax, unused
    const float* Wf = (const float*)d_in[4];
    const float* bf = (const float*)d_in[5];
    const float* Wk = (const float*)d_in[6];
    const float* bk = (const float*)d_in[7];
    const float* Vw = (const float*)d_in[8];
    const float* Vb = (const float*)d_in[9];
    float* out = (float*)d_out;

    cudaFuncSetAttribute(k1_mma, cudaFuncAttributeMaxDynamicSharedMemorySize, SMEM_K1);

    k_prep<<<2145, 256>>>(mainstream, Wc, Wf, bf, Wk, Vw);
    k1_mma<<<256, 512, SMEM_K1>>>(Vb, bk);
    k2_highres<<<1024, 256>>>(contexts, out);
}